// round 14
// baseline (speedup 1.0000x reference)
#include <cuda_runtime.h>

// CVCalculator: sliding-window CV, W=60, ddof=1, eps=1e-6.
// flow (16,4096,64) fp32 -> out (16,4096,64), first 59 time rows zero.
//
// Gold-matching cumsum = XLA ReduceWindowRewriter blocked scan, base 16
// (verified R8/R10/R11/R13). Pole-critical epilogue ops kept exact:
// mean = div.rn(s1,60); denom = fl(mean+1e-6f). Numerator relaxed (rel ~1e-7).
//
// R14: CTA = (batch, feature PAIR) with float2 vectors -> smem 72.6 KB,
// 2 CTAs/SM co-resident (32 warps/SM) to hide the latency that pinned
// R11-R13 at ~25us. Same scan arithmetic per element -> bitwise-identical.

#define T_     4096
#define NT     512
#define BST    34                      // floats per 16-block (16*2 + 2 pad)
#define KSTR   (256 * BST)             // 8704 floats per kind
#define CB     (2 * KSTR)              // carries base (17408)
#define CKSTR  546                     // 16 groups * 34 + pad
#define GB     (CB + 2 * CKSTR)        // group totals base (18500)
#define GKSTR  34
#define SMEM_BYTES ((GB + 2 * GKSTR) * 4)   // 74272 B

__device__ __forceinline__ int taddr(int kind, int t) {
    return kind * KSTR + (t >> 4) * BST + (t & 15) * 2;
}
__device__ __forceinline__ float2 f2addv(float2 a, float2 v) {
    float2 r;
    r.x = __fadd_rn(a.x, v.x); r.y = __fadd_rn(a.y, v.y);
    return r;
}
__device__ __forceinline__ void cp_async8(float* dst, const float* src) {
    unsigned d = (unsigned)__cvta_generic_to_shared(dst);
    asm volatile("cp.async.ca.shared.global [%0], [%1], 8;"
                 :: "r"(d), "l"(src) : "memory");
}

extern "C" __global__ void __launch_bounds__(NT, 2)
cv_kernel(const float* __restrict__ in, float* __restrict__ out)
{
    extern __shared__ float S[];
    const int tid = threadIdx.x;
    const int bat = blockIdx.x >> 5;          // 16 batches
    const int fb  = (blockIdx.x & 31) * 2;    // 32 feature pairs

    const float* __restrict__ gin  = in  + (size_t)bat * T_ * 64 + fb;
    float* __restrict__       gout = out + (size_t)bat * T_ * 64 + fb;

    // ---- stage x once: global -> kind0 region via cp.async (8B) ----
    #pragma unroll
    for (int k = 0; k < 8; ++k) {
        const int t = tid + (k << 9);
        cp_async8(S + taddr(0, t), gin + (size_t)t * 64);
    }
    asm volatile("cp.async.commit_group;" ::: "memory");
    asm volatile("cp.async.wait_group 0;" ::: "memory");
    __syncthreads();

    // ---- P1: read 16-block from kind0 region; square if kind1; scan ----
    const int kind = tid >> 8;
    const int blk  = tid & 255;
    const float* __restrict__ xbase = S + blk * BST;

    float2 r[16];
    #pragma unroll
    for (int i = 0; i < 16; ++i)
        r[i] = *reinterpret_cast<const float2*>(xbase + 2 * i);
    if (kind) {
        #pragma unroll
        for (int i = 0; i < 16; ++i) {
            r[i].x = __fmul_rn(r[i].x, r[i].x);
            r[i].y = __fmul_rn(r[i].y, r[i].y);
        }
    }
    #pragma unroll
    for (int i = 1; i < 16; ++i)
        r[i] = f2addv(r[i - 1], r[i]);
    // block total -> carries
    *reinterpret_cast<float2*>(S + CB + kind * CKSTR + (blk >> 4) * BST
                               + (blk & 15) * 2) = r[15];
    __syncthreads();

    // ---- P2: scan carries within 16-groups (warp 0, lane per (kind,group)) ----
    if (tid < 32) {
        const int kk = tid >> 4, g = tid & 15;
        float* __restrict__ c = S + CB + kk * CKSTR + g * BST;
        float2 v[16];
        #pragma unroll
        for (int i = 0; i < 16; ++i)
            v[i] = *reinterpret_cast<const float2*>(c + 2 * i);
        #pragma unroll
        for (int i = 1; i < 16; ++i)
            v[i] = f2addv(v[i - 1], v[i]);
        #pragma unroll
        for (int i = 0; i < 16; ++i)
            *reinterpret_cast<float2*>(c + 2 * i) = v[i];   // inner1 inclusive
        *reinterpret_cast<float2*>(S + GB + kk * GKSTR + g * 2) = v[15];
    }
    __syncwarp();
    // ---- P3: scan 16 group totals per kind (lanes 0,1) ----
    if (tid < 2) {
        float* __restrict__ gbuf = S + GB + tid * GKSTR;
        float2 v[16];
        #pragma unroll
        for (int g = 0; g < 16; ++g)
            v[g] = *reinterpret_cast<const float2*>(gbuf + 2 * g);
        #pragma unroll
        for (int g = 1; g < 16; ++g)
            v[g] = f2addv(v[g - 1], v[g]);
        #pragma unroll
        for (int g = 0; g < 16; ++g)
            *reinterpret_cast<float2*>(gbuf + 2 * g) = v[g]; // S2 inclusive
    }
    __syncthreads();

    // ---- P5 (P4 folded): cs = fl(S1[blk-1] + inner0), write once ----
    float* __restrict__ base = S + kind * KSTR + blk * BST;
    if (blk > 0) {
        const int pb = blk - 1, pg = pb >> 4;
        float2 carry = *reinterpret_cast<const float2*>(
            S + CB + kind * CKSTR + pg * BST + (pb & 15) * 2);  // inner1[pb]
        if (pg > 0) {
            float2 s2 = *reinterpret_cast<const float2*>(
                S + GB + kind * GKSTR + (pg - 1) * 2);
            // S1[pb] = fl(S2[pg-1] + inner1[pb])
            carry.x = __fadd_rn(s2.x, carry.x);
            carry.y = __fadd_rn(s2.y, carry.y);
        }
        #pragma unroll
        for (int i = 0; i < 16; ++i) {
            float2 v;
            v.x = __fadd_rn(carry.x, r[i].x);
            v.y = __fadd_rn(carry.y, r[i].y);
            *reinterpret_cast<float2*>(base + 2 * i) = v;
        }
    } else {
        #pragma unroll
        for (int i = 0; i < 16; ++i)
            *reinterpret_cast<float2*>(base + 2 * i) = r[i];
    }
    __syncthreads();

    // ---- epilogue: 4x LDS.64 + math + STG.64 per t ----
    #pragma unroll 4
    for (int k = 0; k < 8; ++k) {
        const int t = tid + (k << 9);
        float2 o;
        if (t < 59) {
            o = make_float2(0.f, 0.f);
        } else {
            float2 c1 = *reinterpret_cast<const float2*>(S + taddr(0, t));
            float2 c2 = *reinterpret_cast<const float2*>(S + taddr(1, t));
            float2 p1 = make_float2(0.f, 0.f);
            float2 p2 = make_float2(0.f, 0.f);
            if (t >= 60) {
                p1 = *reinterpret_cast<const float2*>(S + taddr(0, t - 60));
                p2 = *reinterpret_cast<const float2*>(S + taddr(1, t - 60));
            }
            const float* c1a = &c1.x; const float* c2a = &c2.x;
            const float* p1a = &p1.x; const float* p2a = &p2.x;
            float* oa = &o.x;
            #pragma unroll
            for (int f = 0; f < 2; ++f) {
                float s1 = __fsub_rn(c1a[f], p1a[f]);
                float s2 = __fsub_rn(c2a[f], p2a[f]);
                float mean  = __fdiv_rn(s1, 60.0f);      // pole-critical
                float denom = __fadd_rn(mean, 1e-6f);    // pole-critical
                float var = __fmul_rn(__fmaf_rn(-s1, mean, s2), 1.0f / 59.0f);
                float std = (var > 0.0f)
                          ? __fmul_rn(var, __frsqrt_rn(var)) : 0.0f;
                oa[f] = __fdividef(std, denom);
            }
        }
        *reinterpret_cast<float2*>(gout + (size_t)t * 64) = o;
    }
}

extern "C" void kernel_launch(void* const* d_in, const int* in_sizes, int n_in,
                              void* d_out, int out_size) {
    (void)in_sizes; (void)n_in; (void)out_size;
    cudaFuncSetAttribute(cv_kernel, cudaFuncAttributeMaxDynamicSharedMemorySize,
                         SMEM_BYTES);
    cv_kernel<<<512, NT, SMEM_BYTES>>>((const float*)d_in[0], (float*)d_out);
}

// round 15
// speedup vs baseline: 1.4100x; 1.4100x over previous
#include <cuda_runtime.h>

// CVCalculator: sliding-window CV, W=60, ddof=1, eps=1e-6.
// flow (16,4096,64) fp32 -> out (16,4096,64), first 59 time rows zero.
//
// Gold-matching cumsum = XLA ReduceWindowRewriter blocked scan, base 16
// (verified R8/R10/R11/R13). Pole-critical epilogue ops kept exact:
// mean = div.rn(s1,60); denom = fl(mean+1e-6f). Numerator relaxed (rel ~1e-7).
//
// R15: cluster of 2 CTAs splits T=4096 into halves (float4 width kept).
// Identity S1[16g+15] == S2[g] means rank1 only needs S2[7] (1 float4/kind)
// from rank0 to seed its S2 chain + first-block carry, plus a 64-row cs halo
// for its first 60 windows. 76.6 KB smem/CTA -> 2 CTAs/SM co-resident.

#define T_     4096
#define HALF   2048
#define NT     256
#define BST    68                     // floats per 16-block (64 + 4 pad)
#define KSTR   (128 * BST)            // 8704 floats per kind region
#define CB     (2 * KSTR)             // inner1 carries base (17408)
#define CKSTR  (8 * BST)              // 544 floats per kind (8 local groups)
#define GB     (CB + 2 * CKSTR)       // S2 base (18496): 16 global entries/kind
#define GKSTR  68
#define HB     (GB + 2 * GKSTR)       // halo base (18632): 64 float4 per kind
#define HKSTR  256
#define SMEM_BYTES ((HB + 2 * HKSTR) * 4)   // 76576 B

__device__ __forceinline__ int taddr(int kind, int t) {
    return kind * KSTR + (t >> 4) * BST + (t & 15) * 4;
}
__device__ __forceinline__ float4 f4addv(float4 a, float4 v) {
    float4 r;
    r.x = __fadd_rn(a.x, v.x); r.y = __fadd_rn(a.y, v.y);
    r.z = __fadd_rn(a.z, v.z); r.w = __fadd_rn(a.w, v.w);
    return r;
}
__device__ __forceinline__ void cp_async16(float* dst, const float* src) {
    unsigned d = (unsigned)__cvta_generic_to_shared(dst);
    asm volatile("cp.async.cg.shared.global [%0], [%1], 16;"
                 :: "r"(d), "l"(src) : "memory");
}
__device__ __forceinline__ unsigned mapa_rank(unsigned addr, unsigned r) {
    unsigned o;
    asm("mapa.shared::cluster.u32 %0, %1, %2;" : "=r"(o) : "r"(addr), "r"(r));
    return o;
}
__device__ __forceinline__ void st_cluster_f4(unsigned addr, float4 v) {
    unsigned long long lo = ((unsigned long long)__float_as_uint(v.y) << 32)
                          | __float_as_uint(v.x);
    unsigned long long hi = ((unsigned long long)__float_as_uint(v.w) << 32)
                          | __float_as_uint(v.z);
    asm volatile("st.shared::cluster.b64 [%0], %1;" :: "r"(addr), "l"(lo) : "memory");
    asm volatile("st.shared::cluster.b64 [%0], %1;" :: "r"(addr + 8), "l"(hi) : "memory");
}
#define CLUSTER_SYNC() do { \
    asm volatile("barrier.cluster.arrive.aligned;" ::: "memory"); \
    asm volatile("barrier.cluster.wait.aligned;" ::: "memory"); \
} while (0)

extern "C" __global__ void __launch_bounds__(NT, 2) __cluster_dims__(2, 1, 1)
cv_kernel(const float* __restrict__ in, float* __restrict__ out)
{
    extern __shared__ float S[];
    const int tid   = threadIdx.x;
    const int rank  = blockIdx.x & 1;          // cluster ctarank
    const int unit  = blockIdx.x >> 1;         // (batch, feature quad)
    const int bat   = unit >> 4;
    const int fb    = (unit & 15) * 4;
    const int tbase = rank << 11;              // 0 or 2048

    const float* __restrict__ gin  = in  + (size_t)bat * T_ * 64 + fb;
    float* __restrict__       gout = out + (size_t)bat * T_ * 64 + fb;
    const unsigned sbase = (unsigned)__cvta_generic_to_shared(S);

    // ---- stage this half's x into kind0 region via cp.async ----
    #pragma unroll
    for (int k = 0; k < 8; ++k) {
        const int t = tid + (k << 8);
        cp_async16(S + taddr(0, t), gin + (size_t)(tbase + t) * 64);
    }
    asm volatile("cp.async.commit_group;" ::: "memory");
    asm volatile("cp.async.wait_group 0;" ::: "memory");
    __syncthreads();

    // ---- P1: one (kind, local block) per thread; scan in registers ----
    const int kind = tid >> 7;                 // 0..1
    const int blk  = tid & 127;                // local block 0..127
    const float* __restrict__ xbase = S + blk * BST;

    float4 r[16];
    #pragma unroll
    for (int i = 0; i < 16; ++i)
        r[i] = *reinterpret_cast<const float4*>(xbase + 4 * i);
    if (kind) {
        #pragma unroll
        for (int i = 0; i < 16; ++i) {
            r[i].x = __fmul_rn(r[i].x, r[i].x);
            r[i].y = __fmul_rn(r[i].y, r[i].y);
            r[i].z = __fmul_rn(r[i].z, r[i].z);
            r[i].w = __fmul_rn(r[i].w, r[i].w);
        }
    }
    #pragma unroll
    for (int i = 1; i < 16; ++i)
        r[i] = f4addv(r[i - 1], r[i]);
    // block total -> inner1 slot
    *reinterpret_cast<float4*>(S + CB + kind * CKSTR + (blk >> 4) * BST
                               + (blk & 15) * 4) = r[15];
    __syncthreads();

    // ---- P2: scan carries within the 8 local groups (warp 0, 16 lanes) ----
    if (tid < 16) {
        const int kk = tid >> 3, g = tid & 7;
        float* __restrict__ c = S + CB + kk * CKSTR + g * BST;
        float4 v[16];
        #pragma unroll
        for (int i = 0; i < 16; ++i)
            v[i] = *reinterpret_cast<const float4*>(c + 4 * i);
        #pragma unroll
        for (int i = 1; i < 16; ++i)
            v[i] = f4addv(v[i - 1], v[i]);
        #pragma unroll
        for (int i = 0; i < 16; ++i)
            *reinterpret_cast<float4*>(c + 4 * i) = v[i];   // inner1 inclusive
        // group total -> S2 slot at GLOBAL group index
        *reinterpret_cast<float4*>(S + GB + kk * GKSTR
                                   + ((rank << 3) + g) * 4) = v[15];
    }
    __syncwarp();
    // ---- P3 (rank0): chain S2[0..7]; push S2[7] to peer's slot ----
    if (rank == 0 && tid < 2) {
        float* __restrict__ gbuf = S + GB + tid * GKSTR;
        float4 acc = *reinterpret_cast<const float4*>(gbuf);
        #pragma unroll
        for (int g = 1; g < 8; ++g) {
            float4 v = *reinterpret_cast<const float4*>(gbuf + 4 * g);
            acc = f4addv(acc, v);
            *reinterpret_cast<float4*>(gbuf + 4 * g) = acc;
        }
        // remote write: S2[7] into rank1's S2 array
        unsigned la = sbase + (GB + tid * GKSTR + 7 * 4) * 4;
        st_cluster_f4(mapa_rank(la, 1), acc);
    }
    __syncthreads();
    CLUSTER_SYNC();                            // S2[7] visible at rank1

    // ---- rank1: chain S2[8..15] from received S2[7] ----
    if (rank == 1 && tid < 2) {
        float* __restrict__ gbuf = S + GB + tid * GKSTR;
        float4 acc = *reinterpret_cast<const float4*>(gbuf + 7 * 4);
        #pragma unroll
        for (int g = 8; g < 16; ++g) {
            float4 v = *reinterpret_cast<const float4*>(gbuf + 4 * g);
            acc = f4addv(acc, v);
            *reinterpret_cast<float4*>(gbuf + 4 * g) = acc;
        }
    }
    __syncthreads();

    // ---- P5: cs = fl(carry + inner0), write once ----
    float* __restrict__ base = S + kind * KSTR + blk * BST;
    float4 carry;
    bool has_carry = true;
    if (blk > 0) {
        const int pb = blk - 1, pgl = pb >> 4;
        const int gg = (rank << 3) + pgl;
        carry = *reinterpret_cast<const float4*>(
            S + CB + kind * CKSTR + pgl * BST + (pb & 15) * 4);  // inner1[pb]
        if (gg > 0) {
            float4 s2 = *reinterpret_cast<const float4*>(
                S + GB + kind * GKSTR + (gg - 1) * 4);
            carry.x = __fadd_rn(s2.x, carry.x);
            carry.y = __fadd_rn(s2.y, carry.y);
            carry.z = __fadd_rn(s2.z, carry.z);
            carry.w = __fadd_rn(s2.w, carry.w);
        }
    } else if (rank == 1) {
        // S1[global 127] == S2[7]
        carry = *reinterpret_cast<const float4*>(S + GB + kind * GKSTR + 7 * 4);
    } else {
        has_carry = false;
    }
    if (has_carry) {
        #pragma unroll
        for (int i = 0; i < 16; ++i) {
            float4 v;
            v.x = __fadd_rn(carry.x, r[i].x);
            v.y = __fadd_rn(carry.y, r[i].y);
            v.z = __fadd_rn(carry.z, r[i].z);
            v.w = __fadd_rn(carry.w, r[i].w);
            *reinterpret_cast<float4*>(base + 4 * i) = v;
        }
    } else {
        #pragma unroll
        for (int i = 0; i < 16; ++i)
            *reinterpret_cast<float4*>(base + 4 * i) = r[i];
    }
    __syncthreads();

    // ---- rank0: push cs halo (last 64 t, both kinds) to rank1 ----
    if (rank == 0 && tid < 128) {
        const int hk = tid >> 6, i = tid & 63;
        float4 v = *reinterpret_cast<const float4*>(S + taddr(hk, 1984 + i));
        unsigned la = sbase + (HB + hk * HKSTR + i * 4) * 4;
        st_cluster_f4(mapa_rank(la, 1), v);
    }
    CLUSTER_SYNC();                            // halo visible at rank1

    // ---- epilogue ----
    #pragma unroll 4
    for (int k = 0; k < 8; ++k) {
        const int t  = tid + (k << 8);         // local t
        const int tg = tbase + t;              // global t
        float4 o;
        if (tg < 59) {
            o = make_float4(0.f, 0.f, 0.f, 0.f);
        } else {
            float4 c1 = *reinterpret_cast<const float4*>(S + taddr(0, t));
            float4 c2 = *reinterpret_cast<const float4*>(S + taddr(1, t));
            float4 p1 = make_float4(0.f, 0.f, 0.f, 0.f);
            float4 p2 = make_float4(0.f, 0.f, 0.f, 0.f);
            if (t >= 60) {
                p1 = *reinterpret_cast<const float4*>(S + taddr(0, t - 60));
                p2 = *reinterpret_cast<const float4*>(S + taddr(1, t - 60));
            } else if (rank == 1) {
                p1 = *reinterpret_cast<const float4*>(S + HB + (t + 4) * 4);
                p2 = *reinterpret_cast<const float4*>(S + HB + HKSTR + (t + 4) * 4);
            }
            const float* c1a = &c1.x; const float* c2a = &c2.x;
            const float* p1a = &p1.x; const float* p2a = &p2.x;
            float* oa = &o.x;
            #pragma unroll
            for (int f = 0; f < 4; ++f) {
                float s1 = __fsub_rn(c1a[f], p1a[f]);
                float s2 = __fsub_rn(c2a[f], p2a[f]);
                float mean  = __fdiv_rn(s1, 60.0f);      // pole-critical
                float denom = __fadd_rn(mean, 1e-6f);    // pole-critical
                float var = __fmul_rn(__fmaf_rn(-s1, mean, s2), 1.0f / 59.0f);
                float std = (var > 0.0f)
                          ? __fmul_rn(var, __frsqrt_rn(var)) : 0.0f;
                oa[f] = __fdividef(std, denom);
            }
        }
        *reinterpret_cast<float4*>(gout + (size_t)tg * 64) = o;
    }
}

extern "C" void kernel_launch(void* const* d_in, const int* in_sizes, int n_in,
                              void* d_out, int out_size) {
    (void)in_sizes; (void)n_in; (void)out_size;
    cudaFuncSetAttribute(cv_kernel, cudaFuncAttributeMaxDynamicSharedMemorySize,
                         SMEM_BYTES);
    cv_kernel<<<512, NT, SMEM_BYTES>>>((const float*)d_in[0], (float*)d_out);
}

// round 16
// speedup vs baseline: 1.5355x; 1.0890x over previous
#include <cuda_runtime.h>

// CVCalculator: sliding-window CV, W=60, ddof=1, eps=1e-6.
// flow (16,4096,64) fp32 -> out (16,4096,64), first 59 time rows zero.
//
// Gold-matching cumsum = XLA ReduceWindowRewriter blocked scan, base 16
// (verified R8/R10/R11/R13). Scan arithmetic is bitwise-locked.
// Pole-critical epilogue ops:
//   mean  = s1/60 via Markstein 2-fma (correctly rounded for all but
//           measure-zero hard cases; pole-collision risk ~2^-20)
//   denom = fl(mean + 1e-6f)  (exact RN add)
// Numerator relaxed (relative ~1e-7): FMA var, rsqrt, fast divide.
//
// R16 = R13 skeleton + lean epilogue (Markstein mean, peeled boundary iter).

#define T_     4096
#define NT     512
#define KSTR   17408                  // 256 blocks * 68 floats per kind
#define CB     (2 * KSTR)             // carries base  (34816)
#define CKSTR  1104                   // 16 groups * 68 + pad
#define GB     (CB + 2 * CKSTR)       // group-total base (37024)
#define GKSTR  68
#define SMEM_BYTES ((GB + 2 * GKSTR) * 4)   // 148640 B

__device__ __forceinline__ int taddr(int kind, int t) {
    return kind * KSTR + (t >> 4) * 68 + (t & 15) * 4;
}
__device__ __forceinline__ float4 f4addv(float4 a, float4 v) {
    float4 r;
    r.x = __fadd_rn(a.x, v.x); r.y = __fadd_rn(a.y, v.y);
    r.z = __fadd_rn(a.z, v.z); r.w = __fadd_rn(a.w, v.w);
    return r;
}
__device__ __forceinline__ void cp_async16(float* dst, const float* src) {
    unsigned d = (unsigned)__cvta_generic_to_shared(dst);
    asm volatile("cp.async.cg.shared.global [%0], [%1], 16;"
                 :: "r"(d), "l"(src) : "memory");
}

// lean per-element CV: Markstein mean, RN denom, relaxed numerator
__device__ __forceinline__ float cv_elem(float c1, float p1, float c2, float p2) {
    const float C60 = 0.016666667f;            // fl(1/60), correctly rounded
    float s1 = __fsub_rn(c1, p1);
    float s2 = __fsub_rn(c2, p2);
    float q0   = __fmul_rn(s1, C60);
    float rr   = __fmaf_rn(-60.0f, q0, s1);
    float mean = __fmaf_rn(rr, C60, q0);       // == div.rn(s1,60) (Markstein)
    float denom = __fadd_rn(mean, 1e-6f);      // pole-critical, exact
    float var = __fmul_rn(__fmaf_rn(-s1, mean, s2), 1.0f / 59.0f);
    float std = (var > 0.0f) ? __fmul_rn(var, __frsqrt_rn(var)) : 0.0f;
    return __fdividef(std, denom);
}

extern "C" __global__ void __launch_bounds__(NT, 1)
cv_kernel(const float* __restrict__ in, float* __restrict__ out)
{
    extern __shared__ float S[];
    const int tid = threadIdx.x;
    const int bat = blockIdx.x >> 4;
    const int fb  = (blockIdx.x & 15) * 4;

    const float* __restrict__ gin  = in  + (size_t)bat * T_ * 64 + fb;
    float* __restrict__       gout = out + (size_t)bat * T_ * 64 + fb;

    // ---- stage x once: global -> kind0 region via cp.async ----
    #pragma unroll
    for (int k = 0; k < 8; ++k) {
        const int t = tid + (k << 9);
        cp_async16(S + taddr(0, t), gin + (size_t)t * 64);
    }
    asm volatile("cp.async.commit_group;" ::: "memory");
    asm volatile("cp.async.wait_group 0;" ::: "memory");
    __syncthreads();

    // ---- P1: read 16-block from kind0 region; square if kind1; scan ----
    const int kind = tid >> 8;
    const int blk  = tid & 255;
    const float* __restrict__ xbase = S + blk * 68;

    float4 r[16];
    #pragma unroll
    for (int i = 0; i < 16; ++i)
        r[i] = *reinterpret_cast<const float4*>(xbase + 4 * i);
    if (kind) {
        #pragma unroll
        for (int i = 0; i < 16; ++i) {
            r[i].x = __fmul_rn(r[i].x, r[i].x);
            r[i].y = __fmul_rn(r[i].y, r[i].y);
            r[i].z = __fmul_rn(r[i].z, r[i].z);
            r[i].w = __fmul_rn(r[i].w, r[i].w);
        }
    }
    #pragma unroll
    for (int i = 1; i < 16; ++i)
        r[i] = f4addv(r[i - 1], r[i]);
    *reinterpret_cast<float4*>(S + CB + kind * CKSTR + (blk >> 4) * 68
                               + (blk & 15) * 4) = r[15];
    __syncthreads();

    // ---- P2: scan carries within 16-groups (warp 0; prefetch then chain) ----
    if (tid < 32) {
        const int kk = tid >> 4, g = tid & 15;
        float* __restrict__ c = S + CB + kk * CKSTR + g * 68;
        float4 v[16];
        #pragma unroll
        for (int i = 0; i < 16; ++i)
            v[i] = *reinterpret_cast<const float4*>(c + 4 * i);
        #pragma unroll
        for (int i = 1; i < 16; ++i)
            v[i] = f4addv(v[i - 1], v[i]);
        #pragma unroll
        for (int i = 0; i < 16; ++i)
            *reinterpret_cast<float4*>(c + 4 * i) = v[i];   // inner1 inclusive
        *reinterpret_cast<float4*>(S + GB + kk * GKSTR + g * 4) = v[15];
    }
    __syncwarp();
    // ---- P3: scan 16 group totals per kind (lanes 0,1; prefetch+chain) ----
    if (tid < 2) {
        float* __restrict__ gbuf = S + GB + tid * GKSTR;
        float4 v[16];
        #pragma unroll
        for (int g = 0; g < 16; ++g)
            v[g] = *reinterpret_cast<const float4*>(gbuf + 4 * g);
        #pragma unroll
        for (int g = 1; g < 16; ++g)
            v[g] = f4addv(v[g - 1], v[g]);
        #pragma unroll
        for (int g = 0; g < 16; ++g)
            *reinterpret_cast<float4*>(gbuf + 4 * g) = v[g]; // S2 inclusive
    }
    __syncthreads();

    // ---- P5 (P4 folded): cs = fl(S1[blk-1] + inner0), write once ----
    float* __restrict__ base = S + kind * KSTR + blk * 68;
    if (blk > 0) {
        const int pb = blk - 1, pg = pb >> 4;
        float4 carry = *reinterpret_cast<const float4*>(
            S + CB + kind * CKSTR + pg * 68 + (pb & 15) * 4);   // inner1[pb]
        if (pg > 0) {
            float4 s2 = *reinterpret_cast<const float4*>(
                S + GB + kind * GKSTR + (pg - 1) * 4);
            carry.x = __fadd_rn(s2.x, carry.x);
            carry.y = __fadd_rn(s2.y, carry.y);
            carry.z = __fadd_rn(s2.z, carry.z);
            carry.w = __fadd_rn(s2.w, carry.w);
        }
        #pragma unroll
        for (int i = 0; i < 16; ++i) {
            float4 v;
            v.x = __fadd_rn(carry.x, r[i].x);
            v.y = __fadd_rn(carry.y, r[i].y);
            v.z = __fadd_rn(carry.z, r[i].z);
            v.w = __fadd_rn(carry.w, r[i].w);
            *reinterpret_cast<float4*>(base + 4 * i) = v;
        }
    } else {
        #pragma unroll
        for (int i = 0; i < 16; ++i)
            *reinterpret_cast<float4*>(base + 4 * i) = r[i];
    }
    __syncthreads();

    // ---- epilogue: k=0 peeled (boundaries), k=1..7 branch-free ----
    {   // k = 0: t = tid (may be < 60)
        const int t = tid;
        float4 o;
        if (t < 59) {
            o = make_float4(0.f, 0.f, 0.f, 0.f);
        } else {
            float4 c1 = *reinterpret_cast<const float4*>(S + taddr(0, t));
            float4 c2 = *reinterpret_cast<const float4*>(S + taddr(1, t));
            float4 p1 = make_float4(0.f, 0.f, 0.f, 0.f);
            float4 p2 = make_float4(0.f, 0.f, 0.f, 0.f);
            if (t >= 60) {
                p1 = *reinterpret_cast<const float4*>(S + taddr(0, t - 60));
                p2 = *reinterpret_cast<const float4*>(S + taddr(1, t - 60));
            }
            o.x = cv_elem(c1.x, p1.x, c2.x, p2.x);
            o.y = cv_elem(c1.y, p1.y, c2.y, p2.y);
            o.z = cv_elem(c1.z, p1.z, c2.z, p2.z);
            o.w = cv_elem(c1.w, p1.w, c2.w, p2.w);
        }
        *reinterpret_cast<float4*>(gout + (size_t)t * 64) = o;
    }
    #pragma unroll
    for (int k = 1; k < 8; ++k) {      // t >= 512 > 60 always
        const int t = tid + (k << 9);
        float4 c1 = *reinterpret_cast<const float4*>(S + taddr(0, t));
        float4 c2 = *reinterpret_cast<const float4*>(S + taddr(1, t));
        float4 p1 = *reinterpret_cast<const float4*>(S + taddr(0, t - 60));
        float4 p2 = *reinterpret_cast<const float4*>(S + taddr(1, t - 60));
        float4 o;
        o.x = cv_elem(c1.x, p1.x, c2.x, p2.x);
        o.y = cv_elem(c1.y, p1.y, c2.y, p2.y);
        o.z = cv_elem(c1.z, p1.z, c2.z, p2.z);
        o.w = cv_elem(c1.w, p1.w, c2.w, p2.w);
        *reinterpret_cast<float4*>(gout + (size_t)t * 64) = o;
    }
}

extern "C" void kernel_launch(void* const* d_in, const int* in_sizes, int n_in,
                              void* d_out, int out_size) {
    (void)in_sizes; (void)n_in; (void)out_size;
    cudaFuncSetAttribute(cv_kernel, cudaFuncAttributeMaxDynamicSharedMemorySize,
                         SMEM_BYTES);
    cv_kernel<<<256, NT, SMEM_BYTES>>>((const float*)d_in[0], (float*)d_out);
}